// round 10
// baseline (speedup 1.0000x reference)
#include <cuda_runtime.h>

// Problem constants
#define B_TOT 2048
#define T_LEN 128
#define DIN   64
#define UDIM  128
#define NG    512   // 4*U
#define KTOT  192   // DIN + U
#define BT    16    // batch rows per CTA
#define NTH   128   // each thread: 4 adjacent gate columns x all 16 rows
#define XH_S  20    // row stride for [x|h] tile (floats)
#define GSW   516   // gate staging row stride: [16 rows][512 cols + 4 pad]
#define KUF   4     // weight prefetch block (double-buffered)

#define SMEM_XH (KTOT * XH_S)          // 3840 floats
#define SMEM_GS (BT * GSW)             // 8256 floats
#define SMEM_FLOATS (SMEM_XH + SMEM_GS) // 12096 floats = 48384 B (< 48KB static limit)

// Pre-transposed fused weights: g_Wt[k][n], k<64 -> W_ih, else W_hh
__device__ __align__(16) float g_Wt[KTOT * NG];
__device__ __align__(16) float g_bias[NG];

__global__ void prep_kernel(const float* __restrict__ W_ih, const float* __restrict__ W_hh,
                            const float* __restrict__ b_ih, const float* __restrict__ b_hh) {
    int k = blockIdx.x;
    int n = threadIdx.x;
    g_Wt[k * NG + n] = (k < DIN) ? W_ih[n * DIN + k] : W_hh[n * UDIM + (k - DIN)];
    if (k == 0) g_bias[n] = b_ih[n] + b_hh[n];
}

__device__ __forceinline__ float fsig(float x) {
    return 1.0f / (1.0f + __expf(-x));
}
__device__ __forceinline__ float ftanh(float x) {
    float a = fabsf(x);
    float e = __expf(2.0f * a);
    float r = 1.0f - 2.0f / (1.0f + e);
    return copysignf(r, x);
}

// packed fp32x2 FMA (sm_100a): d = a*b + d  (same fp32 RN rounding as FFMA)
#define FFMA2(d, a, b) \
    asm("fma.rn.f32x2 %0, %1, %2, %0;" : "+l"(d) : "l"(a), "l"(b))

__device__ __forceinline__ unsigned long long splat2(float w) {
    unsigned long long r;
    asm("mov.b64 %0, {%1, %1};" : "=l"(r) : "f"(w));
    return r;
}
__device__ __forceinline__ void unpack2(unsigned long long p, float& lo, float& hi) {
    asm("mov.b64 {%0, %1}, %2;" : "=f"(lo), "=f"(hi) : "l"(p));
}

__global__ void __launch_bounds__(NTH, 2)
lstm_kernel(const float* __restrict__ x_st, const float* __restrict__ x_sc,
            const float* __restrict__ bn_gamma, const float* __restrict__ bn_beta,
            const float* __restrict__ bn_mean, const float* __restrict__ bn_var,
            float* __restrict__ out) {
    // sxh: [192][XH_S]  rows 0..63 = x_t ([k][b]), rows 64..191 = h ([u][b])
    // sgs: [16][GSW]    activated gates, TRANSPOSED: [b][n]  (coalesced STS/LDS)
    __shared__ __align__(16) float sxh[SMEM_XH];
    __shared__ __align__(16) float sgs[SMEM_GS];

    const int path  = blockIdx.y;            // 0 = SNN (st), 1 = ANN (sc)
    const int bbase = blockIdx.x * BT;
    const float* __restrict__ xin = (path == 0) ? x_st : x_sc;
    const float* __restrict__ xrow = xin + (size_t)bbase * T_LEN * DIN;

    const int i = threadIdx.x;               // owns gate cols 4i..4i+3, ALL 16 rows
    const int g = i >> 5;                    // gate of those 4 cols: 0:i 1:f 2:g 3:o
    // state mapping: thread owns u=i for ALL 16 batch rows (c,m,s in registers)

    // x staging: 1024 elems, 8 per thread: k = i&63 fixed, b = (i>>6) + 2r
    const int xk  = i & 63;
    const int xb0 = i >> 6;

    // zero the [x|h] tile (h rows start at 0, pads stay 0)
    for (int idx = i; idx < SMEM_XH; idx += NTH) sxh[idx] = 0.0f;
    __syncthreads();

    // stage x_0 (after zeroing barrier, before main-loop barrier A)
#pragma unroll
    for (int r = 0; r < 8; r++) {
        int b = xb0 + 2 * r;
        sxh[xk * XH_S + b] = xrow[((size_t)b * T_LEN + 0) * DIN + xk];
    }

    float c[16], m[16], s[16];
#pragma unroll
    for (int j = 0; j < 16; j++) { c[j] = 0.0f; m[j] = 0.0f; s[j] = 0.0f; }

    // bias for the 4 owned columns, pre-splatted
    unsigned long long biasp[4];
    {
        float4 bv = __ldg(((const float4*)g_bias) + i);
        biasp[0] = splat2(bv.x); biasp[1] = splat2(bv.y);
        biasp[2] = splat2(bv.z); biasp[3] = splat2(bv.w);
    }

    // weight stream: float4 (4 cols) per k per thread, double-buffered
    const float4* __restrict__ Wp = (const float4*)g_Wt;   // [k][128] float4
    float4 w[KUF], wn[KUF];
#pragma unroll
    for (int q = 0; q < KUF; q++) w[q] = __ldg(Wp + (size_t)q * (NG / 4) + i);

    for (int t = 0; t < T_LEN; t++) {
        __syncthreads();   // (A) x_t and h_t visible to everyone

        // ---- gates[b][n] = sum_k xh[k][b] * Wt[k][n] + bias; 4 cols x 16 rows ----
        unsigned long long acc[4][8];
#pragma unroll
        for (int cc = 0; cc < 4; cc++)
#pragma unroll
            for (int p = 0; p < 8; p++) acc[cc][p] = biasp[cc];

#pragma unroll 2
        for (int kb = 0; kb < KTOT; kb += KUF) {
            // prefetch next block; final block wraps to block 0 (ready for next t)
            int kn = (kb + KUF < KTOT) ? (kb + KUF) : 0;
#pragma unroll
            for (int q = 0; q < KUF; q++)
                wn[q] = __ldg(Wp + (size_t)(kn + q) * (NG / 4) + i);
#pragma unroll
            for (int q = 0; q < KUF; q++) {
                const ulonglong2* xr = (const ulonglong2*)(sxh + (kb + q) * XH_S);
                ulonglong2 q0 = xr[0];   // batch pairs (0,1),(2,3)   -- broadcast
                ulonglong2 q1 = xr[1];   // (4,5),(6,7)
                ulonglong2 q2 = xr[2];   // (8,9),(10,11)
                ulonglong2 q3 = xr[3];   // (12,13),(14,15)
                const float* wf = (const float*)&w[q];
#pragma unroll
                for (int cc = 0; cc < 4; cc++) {
                    unsigned long long wc = splat2(wf[cc]);
                    FFMA2(acc[cc][0], q0.x, wc);
                    FFMA2(acc[cc][1], q0.y, wc);
                    FFMA2(acc[cc][2], q1.x, wc);
                    FFMA2(acc[cc][3], q1.y, wc);
                    FFMA2(acc[cc][4], q2.x, wc);
                    FFMA2(acc[cc][5], q2.y, wc);
                    FFMA2(acc[cc][6], q3.x, wc);
                    FFMA2(acc[cc][7], q3.y, wc);
                }
            }
#pragma unroll
            for (int q = 0; q < KUF; q++) w[q] = wn[q];
        }

        // ---- prefetch next step's x (acc regs free soon; consumed after barrier B) ----
        float rx[8];
        if (t + 1 < T_LEN) {
#pragma unroll
            for (int r = 0; r < 8; r++) {
                int b = xb0 + 2 * r;
                rx[r] = xrow[((size_t)b * T_LEN + (t + 1)) * DIN + xk];
            }
        }

        // ---- activations (64 values) ----
        float v[4][16];
#pragma unroll
        for (int cc = 0; cc < 4; cc++)
#pragma unroll
            for (int p = 0; p < 8; p++)
                unpack2(acc[cc][p], v[cc][2 * p], v[cc][2 * p + 1]);
        if (g == 2) {
#pragma unroll
            for (int cc = 0; cc < 4; cc++)
#pragma unroll
                for (int b = 0; b < 16; b++) v[cc][b] = ftanh(v[cc][b]);
        } else {
#pragma unroll
            for (int cc = 0; cc < 4; cc++)
#pragma unroll
                for (int b = 0; b < 16; b++) v[cc][b] = fsig(v[cc][b]);
        }

        // ---- stage gates, transposed layout [b][n]: coalesced STS.128 ----
#pragma unroll
        for (int b = 0; b < 16; b++) {
            ((float4*)(sgs + b * GSW))[i] =
                make_float4(v[0][b], v[1][b], v[2][b], v[3][b]);
        }
        __syncthreads();   // (B) all gates visible; all gemm reads of sxh done

        // ---- stage next x_t (safe: gemm reads finished) ----
        if (t + 1 < T_LEN) {
#pragma unroll
            for (int r = 0; r < 8; r++) sxh[xk * XH_S + xb0 + 2 * r] = rx[r];
        }

        // ---- state update: thread owns u=i, all 16 rows (coalesced LDS.32) ----
        if (path) {        // ANN: h = o * tanh(c)
#pragma unroll
            for (int b = 0; b < 16; b++) {
                float ig = sgs[b * GSW + 0 * UDIM + i];
                float fg = sgs[b * GSW + 1 * UDIM + i];
                float gg = sgs[b * GSW + 2 * UDIM + i];
                float og = sgs[b * GSW + 3 * UDIM + i];
                c[b] = fg * c[b] + ig * gg;
                float hv = og * ftanh(c[b]);
                s[b] += hv;
                sxh[(DIN + i) * XH_S + b] = hv;
            }
        } else {           // SNN: integrate-and-fire, spikes feed back as h
#pragma unroll
            for (int b = 0; b < 16; b++) {
                float ig = sgs[b * GSW + 0 * UDIM + i];
                float fg = sgs[b * GSW + 1 * UDIM + i];
                float gg = sgs[b * GSW + 2 * UDIM + i];
                float og = sgs[b * GSW + 3 * UDIM + i];
                c[b] = fg * c[b] + ig * gg;
                m[b] += og * ftanh(c[b]);
                float spk = (m[b] >= 1.0f) ? 1.0f : 0.0f;
                m[b] -= spk;
                s[b] += spk;
                sxh[(DIN + i) * XH_S + b] = spk;
            }
        }
        // next iteration's barrier (A) orders h/x writes before the next gemm
    }

    // ---- epilogue: temporal mean + BatchNorm (eval mode) ----
    float scale = bn_gamma[i] * rsqrtf(bn_var[i] + 1e-5f);
    float shift = bn_beta[i] - bn_mean[i] * scale;
    const float inv = 1.0f / (float)T_LEN;
#pragma unroll
    for (int b = 0; b < 16; b++) {
        out[((size_t)path * B_TOT + bbase + b) * UDIM + i] = s[b] * inv * scale + shift;
    }
}

extern "C" void kernel_launch(void* const* d_in, const int* in_sizes, int n_in,
                              void* d_out, int out_size) {
    const float* x_st  = (const float*)d_in[0];
    const float* x_sc  = (const float*)d_in[1];
    const float* W_ih  = (const float*)d_in[2];
    const float* W_hh  = (const float*)d_in[3];
    const float* b_ih  = (const float*)d_in[4];
    const float* b_hh  = (const float*)d_in[5];
    const float* gamma = (const float*)d_in[6];
    const float* beta  = (const float*)d_in[7];
    const float* mean  = (const float*)d_in[8];
    const float* var   = (const float*)d_in[9];

    prep_kernel<<<KTOT, NG>>>(W_ih, W_hh, b_ih, b_hh);

    dim3 grid(B_TOT / BT, 2);   // (128, 2) = 256 CTAs, 2 per SM
    lstm_kernel<<<grid, NTH>>>(x_st, x_sc, gamma, beta, mean, var, (float*)d_out);
}

// round 11
// speedup vs baseline: 1.0606x; 1.0606x over previous
#include <cuda_runtime.h>

// Problem constants
#define B_TOT 2048
#define T_LEN 128
#define DIN   64
#define UDIM  128
#define NG    512   // 4*U
#define KTOT  192   // DIN + U
#define BT    16    // batch rows per CTA
#define NTH   128   // thread i owns unit u=i: gate cols {i,128+i,256+i,384+i}, all 16 rows
#define XH_S  20    // row stride for [x|h] tile (floats)
#define KUF   4     // weight prefetch block (double-buffered)
#define BUFSZ (KTOT * XH_S)   // 3840 floats per buffer

// Permuted fused weights: g_Wt[k][i*4+g] = W_gate_g_row_i[k]  (k<64: W_ih, else W_hh)
// -> thread i reads one float4 per k covering its 4 gate columns, coalesced.
__device__ __align__(16) float g_Wt[KTOT * NG];
__device__ __align__(16) float g_bias[NG];

__global__ void prep_kernel(const float* __restrict__ W_ih, const float* __restrict__ W_hh,
                            const float* __restrict__ b_ih, const float* __restrict__ b_hh) {
    int k = blockIdx.x;
    int n = threadIdx.x;                     // torch gate-major index: gate = n>>7, unit = n&127
    int perm = (n & 127) * 4 + (n >> 7);     // unit-major permuted slot
    g_Wt[k * NG + perm] = (k < DIN) ? W_ih[n * DIN + k] : W_hh[n * UDIM + (k - DIN)];
    if (k == 0) g_bias[perm] = b_ih[n] + b_hh[n];
}

__device__ __forceinline__ float fsig(float x) {
    return 1.0f / (1.0f + __expf(-x));
}
__device__ __forceinline__ float ftanh(float x) {
    float a = fabsf(x);
    float e = __expf(2.0f * a);
    float r = 1.0f - 2.0f / (1.0f + e);
    return copysignf(r, x);
}

// packed fp32x2 FMA (sm_100a): d = a*b + d  (same fp32 RN rounding as FFMA)
#define FFMA2(d, a, b) \
    asm("fma.rn.f32x2 %0, %1, %2, %0;" : "+l"(d) : "l"(a), "l"(b))

__device__ __forceinline__ unsigned long long splat2(float w) {
    unsigned long long r;
    asm("mov.b64 %0, {%1, %1};" : "=l"(r) : "f"(w));
    return r;
}
__device__ __forceinline__ void unpack2(unsigned long long p, float& lo, float& hi) {
    asm("mov.b64 {%0, %1}, %2;" : "=f"(lo), "=f"(hi) : "l"(p));
}

__global__ void __launch_bounds__(NTH, 2)
lstm_kernel(const float* __restrict__ x_st, const float* __restrict__ x_sc,
            const float* __restrict__ bn_gamma, const float* __restrict__ bn_beta,
            const float* __restrict__ bn_mean, const float* __restrict__ bn_var,
            float* __restrict__ out) {
    // Double-buffered [x|h] tile: per buffer, rows 0..63 = x_t ([k][b]),
    // rows 64..191 = h ([u][b]). Step t reads buf (t&1), writes buf (1-(t&1)).
    // Single barrier per step; no gate staging (gates stay in registers).
    __shared__ __align__(16) float sxh[2 * BUFSZ];   // 30720 B

    const int path  = blockIdx.y;            // 0 = SNN (st), 1 = ANN (sc)
    const int bbase = blockIdx.x * BT;
    const float* __restrict__ xin = (path == 0) ? x_st : x_sc;
    const float* __restrict__ xrow = xin + (size_t)bbase * T_LEN * DIN;

    const int i = threadIdx.x;               // unit u = i; owns all 16 batch rows

    // x staging: 1024 elems (64 k x 16 b), 8 per thread: k fixed, b = (i>>6) + 2r
    const int xk  = i & 63;
    const int xb0 = i >> 6;

    // zero both buffers (h starts at 0, pads stay 0)
    for (int idx = i; idx < 2 * BUFSZ; idx += NTH) sxh[idx] = 0.0f;
    __syncthreads();

    // stage x_0 into buffer 0
#pragma unroll
    for (int r = 0; r < 8; r++) {
        int b = xb0 + 2 * r;
        sxh[xk * XH_S + b] = xrow[((size_t)b * T_LEN + 0) * DIN + xk];
    }

    float c[16], m[16], s[16];
#pragma unroll
    for (int j = 0; j < 16; j++) { c[j] = 0.0f; m[j] = 0.0f; s[j] = 0.0f; }

    // bias for this unit's 4 gates (i,f,g,o), pre-splatted
    unsigned long long biasp[4];
    {
        float4 bv = __ldg(((const float4*)g_bias) + i);
        biasp[0] = splat2(bv.x); biasp[1] = splat2(bv.y);
        biasp[2] = splat2(bv.z); biasp[3] = splat2(bv.w);
    }

    // weight stream: one float4 (4 gate cols of unit i) per k, double-buffered
    const float4* __restrict__ Wp = (const float4*)g_Wt;   // [k][128] float4
    float4 w[KUF], wn[KUF];
#pragma unroll
    for (int q = 0; q < KUF; q++) w[q] = __ldg(Wp + (size_t)q * (NG / 4) + i);

    for (int t = 0; t < T_LEN; t++) {
        const float* __restrict__ rd = sxh + (t & 1) * BUFSZ;
        float* __restrict__ wr       = sxh + ((t + 1) & 1) * BUFSZ;

        __syncthreads();   // (A) x_t and h_t in rd-buffer visible; wr-buffer free

        // ---- gates for unit i, 16 rows: acc[g][pair] over k ----
        unsigned long long acc[4][8];
#pragma unroll
        for (int g = 0; g < 4; g++)
#pragma unroll
            for (int p = 0; p < 8; p++) acc[g][p] = biasp[g];

#pragma unroll 2
        for (int kb = 0; kb < KTOT; kb += KUF) {
            // prefetch next block; final block wraps to 0 (ready for next t)
            int kn = (kb + KUF < KTOT) ? (kb + KUF) : 0;
#pragma unroll
            for (int q = 0; q < KUF; q++)
                wn[q] = __ldg(Wp + (size_t)(kn + q) * (NG / 4) + i);
#pragma unroll
            for (int q = 0; q < KUF; q++) {
                const ulonglong2* xr = (const ulonglong2*)(rd + (kb + q) * XH_S);
                ulonglong2 q0 = xr[0];   // batch pairs (0,1),(2,3)   -- broadcast LDS
                ulonglong2 q1 = xr[1];   // (4,5),(6,7)
                ulonglong2 q2 = xr[2];   // (8,9),(10,11)
                ulonglong2 q3 = xr[3];   // (12,13),(14,15)
                const float* wf = (const float*)&w[q];
#pragma unroll
                for (int g = 0; g < 4; g++) {
                    unsigned long long wc = splat2(wf[g]);
                    FFMA2(acc[g][0], q0.x, wc);
                    FFMA2(acc[g][1], q0.y, wc);
                    FFMA2(acc[g][2], q1.x, wc);
                    FFMA2(acc[g][3], q1.y, wc);
                    FFMA2(acc[g][4], q2.x, wc);
                    FFMA2(acc[g][5], q2.y, wc);
                    FFMA2(acc[g][6], q3.x, wc);
                    FFMA2(acc[g][7], q3.y, wc);
                }
            }
#pragma unroll
            for (int q = 0; q < KUF; q++) w[q] = wn[q];
        }

        // ---- prefetch next step's x, stage into wr (nobody reads wr this step) ----
        if (t + 1 < T_LEN) {
            float rx[8];
#pragma unroll
            for (int r = 0; r < 8; r++) {
                int b = xb0 + 2 * r;
                rx[r] = xrow[((size_t)b * T_LEN + (t + 1)) * DIN + xk];
            }
#pragma unroll
            for (int r = 0; r < 8; r++) wr[xk * XH_S + xb0 + 2 * r] = rx[r];
        }

        // ---- activations: all gates in registers, no smem round-trip ----
        float ig[16], fg[16], gg[16], og[16];
#pragma unroll
        for (int p = 0; p < 8; p++) {
            unpack2(acc[0][p], ig[2 * p], ig[2 * p + 1]);
            unpack2(acc[1][p], fg[2 * p], fg[2 * p + 1]);
            unpack2(acc[2][p], gg[2 * p], gg[2 * p + 1]);
            unpack2(acc[3][p], og[2 * p], og[2 * p + 1]);
        }
#pragma unroll
        for (int b = 0; b < 16; b++) {
            ig[b] = fsig(ig[b]);
            fg[b] = fsig(fg[b]);
            gg[b] = ftanh(gg[b]);
            og[b] = fsig(og[b]);
        }

        // ---- state update in registers; h written straight to wr ----
        float hv[16];
        if (path) {        // ANN: h = o * tanh(c)
#pragma unroll
            for (int b = 0; b < 16; b++) {
                c[b] = fg[b] * c[b] + ig[b] * gg[b];
                hv[b] = og[b] * ftanh(c[b]);
                s[b] += hv[b];
            }
        } else {           // SNN: integrate-and-fire, spikes feed back as h
#pragma unroll
            for (int b = 0; b < 16; b++) {
                c[b] = fg[b] * c[b] + ig[b] * gg[b];
                m[b] += og[b] * ftanh(c[b]);
                float spk = (m[b] >= 1.0f) ? 1.0f : 0.0f;
                m[b] -= spk;
                hv[b] = spk;
                s[b] += spk;
            }
        }
        {
            float4* hw = (float4*)(wr + (DIN + i) * XH_S);
            hw[0] = make_float4(hv[0],  hv[1],  hv[2],  hv[3]);
            hw[1] = make_float4(hv[4],  hv[5],  hv[6],  hv[7]);
            hw[2] = make_float4(hv[8],  hv[9],  hv[10], hv[11]);
            hw[3] = make_float4(hv[12], hv[13], hv[14], hv[15]);
        }
        // next iteration's barrier (A) publishes wr before it is read
    }

    // ---- epilogue: temporal mean + BatchNorm (eval mode) ----
    float scale = bn_gamma[i] * rsqrtf(bn_var[i] + 1e-5f);
    float shift = bn_beta[i] - bn_mean[i] * scale;
    const float inv = 1.0f / (float)T_LEN;
#pragma unroll
    for (int b = 0; b < 16; b++) {
        out[((size_t)path * B_TOT + bbase + b) * UDIM + i] = s[b] * inv * scale + shift;
    }
}

extern "C" void kernel_launch(void* const* d_in, const int* in_sizes, int n_in,
                              void* d_out, int out_size) {
    const float* x_st  = (const float*)d_in[0];
    const float* x_sc  = (const float*)d_in[1];
    const float* W_ih  = (const float*)d_in[2];
    const float* W_hh  = (const float*)d_in[3];
    const float* b_ih  = (const float*)d_in[4];
    const float* b_hh  = (const float*)d_in[5];
    const float* gamma = (const float*)d_in[6];
    const float* beta  = (const float*)d_in[7];
    const float* mean  = (const float*)d_in[8];
    const float* var   = (const float*)d_in[9];

    prep_kernel<<<KTOT, NG>>>(W_ih, W_hh, b_ih, b_hh);

    dim3 grid(B_TOT / BT, 2);   // (128, 2) = 256 CTAs, 2 per SM
    lstm_kernel<<<grid, NTH>>>(x_st, x_sc, gamma, beta, mean, var, (float*)d_out);
}